// round 16
// baseline (speedup 1.0000x reference)
#include <cuda_runtime.h>
#include <cuda_bf16.h>
#include <cuda_fp16.h>
#include <cstdint>
#include <cstddef>

#define BB 128
#define TT 2048
#define II 64
#define HH 128
#define GG 512                 // 4*H
#define BT (BB * TT)

// ---- recurrence config: 256 threads, 2 rows/thread --------------------------
#define REGK 104               // W_hh cols per row held in registers (RF boundary)
#define SMEMK (HH - REGK)      // 24 cols in SMEM, stored as fp16
#define NW64 (SMEMK / 8)       // 3 groups of 8 fp16 cols per row (2 u64 planes)

typedef unsigned long long u64;

// 512MB scratch for x_proj[row][g], row = b*T + t, g in [0,512)
__device__ float g_xproj[(size_t)BT * GG];

__device__ __forceinline__ u64 pk(float lo, float hi) {
    u64 r; asm("mov.b64 %0,{%1,%2};" : "=l"(r) : "f"(lo), "f"(hi)); return r;
}
__device__ __forceinline__ void upk(u64 v, float& lo, float& hi) {
    asm("mov.b64 {%0,%1},%2;" : "=f"(lo), "=f"(hi) : "l"(v));
}
// packed fp32x2 FMA (sm_103a): d.lo += a.lo*b.lo ; d.hi += a.hi*b.hi
__device__ __forceinline__ void fma2(u64& d, u64 a, u64 b) {
    asm("fma.rn.f32x2 %0,%1,%2,%0;" : "+l"(d) : "l"(a), "l"(b));
}
// half2 (packed in u32) -> f32x2 pair packed in u64
__device__ __forceinline__ u64 h2f2(unsigned int h2) {
    float2 f = __half22float2(*reinterpret_cast<__half2*>(&h2));
    return pk(f.x, f.y);
}

// HW tanh (MUFU-class single op, rel err ~2^-10.8)
__device__ __forceinline__ float tanh_ap(float x) {
    float y; asm("tanh.approx.f32 %0, %1;" : "=f"(y) : "f"(x)); return y;
}
__device__ __forceinline__ float sigmoid_ap(float x) {
    return fmaf(0.5f, tanh_ap(0.5f * x), 0.5f);
}

// ---------------------------------------------------------------------------
// Phase 1: g_xproj[row][512] = W_ih @ x[row] + (b_ih + b_hh)   (unchanged)
// ---------------------------------------------------------------------------
__global__ __launch_bounds__(512, 1) void xproj_kernel(
    const float* __restrict__ x, const float* __restrict__ Wih,
    const float* __restrict__ bih, const float* __restrict__ bhh)
{
    extern __shared__ float sm1[];
    float* wsg  = sm1;                   // [64][512] k-major
    float* bsum = wsg + 64 * 512;        // [512]
    float* xs   = bsum + 512;            // [64 k][68 rows] padded

    const int tid = threadIdx.x;

    for (int idx = tid; idx < 64 * 512; idx += 512) {
        int k = idx >> 9, c = idx & 511;
        wsg[idx] = Wih[c * 64 + k];
    }
    bsum[tid] = bih[tid] + bhh[tid];
    __syncthreads();

    const int lane = tid & 31, wrp = tid >> 5;
    const int r0 = (wrp & 7) * 8;
    const int cb = (wrp >> 3) * 256 + lane * 4;

    u64 bp[4];
    {
        float4 t0 = *(const float4*)&bsum[cb];
        float4 t1 = *(const float4*)&bsum[cb + 128];
        bp[0] = pk(t0.x, t0.y); bp[1] = pk(t0.z, t0.w);
        bp[2] = pk(t1.x, t1.y); bp[3] = pk(t1.z, t1.w);
    }

    for (int tile = blockIdx.x; tile < BT / 64; tile += gridDim.x) {
        __syncthreads();
        for (int idx = tid; idx < 64 * 64; idx += 512) {
            int r = idx >> 6, k = idx & 63;
            xs[k * 68 + r] = x[(size_t)tile * 64 * 64 + idx];
        }
        __syncthreads();

        u64 acc[8][4];
        #pragma unroll
        for (int ri = 0; ri < 8; ri++) {
            acc[ri][0] = bp[0]; acc[ri][1] = bp[1];
            acc[ri][2] = bp[2]; acc[ri][3] = bp[3];
        }

        #pragma unroll 8
        for (int k = 0; k < 64; k++) {
            ulonglong2 wv0 = *(const ulonglong2*)&wsg[k * 512 + cb];
            ulonglong2 wv1 = *(const ulonglong2*)&wsg[k * 512 + cb + 128];
            float4 xa = *(const float4*)&xs[k * 68 + r0];
            float4 xb = *(const float4*)&xs[k * 68 + r0 + 4];
            float xv[8] = {xa.x, xa.y, xa.z, xa.w, xb.x, xb.y, xb.z, xb.w};
            #pragma unroll
            for (int ri = 0; ri < 8; ri++) {
                u64 xx = pk(xv[ri], xv[ri]);
                fma2(acc[ri][0], wv0.x, xx); fma2(acc[ri][1], wv0.y, xx);
                fma2(acc[ri][2], wv1.x, xx); fma2(acc[ri][3], wv1.y, xx);
            }
        }

        #pragma unroll
        for (int ri = 0; ri < 8; ri++) {
            size_t row = (size_t)tile * 64 + r0 + ri;
            float a0,a1,a2,a3,a4,a5,a6,a7;
            upk(acc[ri][0], a0, a1); upk(acc[ri][1], a2, a3);
            upk(acc[ri][2], a4, a5); upk(acc[ri][3], a6, a7);
            *(float4*)&g_xproj[row * GG + cb]       = make_float4(a0,a1,a2,a3);
            *(float4*)&g_xproj[row * GG + cb + 128] = make_float4(a4,a5,a6,a7);
        }
    }
}

// ---------------------------------------------------------------------------
// Phase 2: LSTM recurrence. One CTA per batch (128 CTAs, one wave).
// 256 threads; thread tid owns gate rows tid and tid+256; threads tid and
// tid+128 together hold all 4 gates of hidden unit jh = tid & 127.
// W_hh[row][0:104] in registers (2 x 52 u64); [104:128) in SMEM as fp16 in
// TWO u64 planes of [NW64][512]:
//   plane0[q*512+r] = cols[104+8q .. 107+8q], plane1 = cols[108+8q .. 111+8q]
// -> 6 LDS.64/thread (24KB total, half the f32 crossbar bandwidth).
// h broadcast as LDS.128 pairs; activations gathered as float4 {i,g,f,o}.
// SMEM: wsh 2*3*512*8 = 24576, h 2*128*4 = 1024, gQ 128*16 = 2048 -> 27648B
// ---------------------------------------------------------------------------
__global__ __launch_bounds__(256, 1) void lstm_kernel(
    const float* __restrict__ Whh, const float* __restrict__ h0,
    const float* __restrict__ c0, float* __restrict__ out)
{
    extern __shared__ char sm2c[];
    u64*   wsh = (u64*)sm2c;                            // 2 planes [NW64][512]
    float* h_s = (float*)(sm2c + 2 * NW64 * 512 * 8);   // [2][128]  (FIXED base)
    float* gQ  = h_s + 2 * HH;                          // [128][4] {i,g,f,o}

    const int tid = threadIdx.x;          // 0..255
    const int jh  = tid & 127;            // hidden unit index
    const int b   = blockIdx.x;
    const int rA  = tid;                  // row A: i (tid<128) or f
    const int rB  = tid + 256;            // row B: g (tid<128) or o

    // --- register weights: rows rA, rB cols [0,104) as 52 u64 each ---
    u64 wA[REGK / 2], wB[REGK / 2];
    {
        const float* a  = Whh + rA * HH;
        const float* bq = Whh + rB * HH;
        #pragma unroll
        for (int q = 0; q < REGK / 4; q++) {
            float4 v = *(const float4*)&a[4 * q];
            wA[2 * q] = pk(v.x, v.y); wA[2 * q + 1] = pk(v.z, v.w);
            float4 w = *(const float4*)&bq[4 * q];
            wB[2 * q] = pk(w.x, w.y); wB[2 * q + 1] = pk(w.z, w.w);
        }
    }
    // --- SMEM fp16 weights, two planes ---
    for (int idx = tid; idx < NW64 * 512; idx += 256) {
        int q = idx >> 9, r = idx & 511;
        const float* wr = &Whh[r * HH + REGK + 8 * q];
        __half2 p0 = __floats2half2_rn(wr[0], wr[1]);
        __half2 p1 = __floats2half2_rn(wr[2], wr[3]);
        __half2 p2 = __floats2half2_rn(wr[4], wr[5]);
        __half2 p3 = __floats2half2_rn(wr[6], wr[7]);
        unsigned int u0 = *(unsigned int*)&p0, u1 = *(unsigned int*)&p1;
        unsigned int u2 = *(unsigned int*)&p2, u3 = *(unsigned int*)&p3;
        wsh[idx]               = ((u64)u1 << 32) | u0;   // cols 104+8q..107+8q
        wsh[NW64 * 512 + idx]  = ((u64)u3 << 32) | u2;   // cols 108+8q..111+8q
    }
    // --- initial state (both partner threads carry c redundantly) ---
    float c = c0[b * HH + jh];
    if (tid < HH) h_s[tid] = h0[b * HH + tid];
    __syncthreads();

    const float* xp = g_xproj + (size_t)b * TT * GG;
    float* enc = out + BB * HH + (size_t)b * TT * HH;

    int p = 0;
    float xgA = xp[rA];                    // prefetch t = 0
    float xgB = xp[rB];
    for (int t = 0; t < TT; t++) {
        float xa = xgA, xb = xgB;
        if (t + 1 < TT) {                  // prefetch next step
            xgA = xp[(size_t)(t + 1) * GG + rA];
            xgB = xp[(size_t)(t + 1) * GG + rB];
        }

        const ulonglong2* hb2 = (const ulonglong2*)&h_s[p * HH];  // 32 pairs
        u64 aA0 = 0ULL, aA1 = 0ULL, aB0 = 0ULL, aB1 = 0ULL;

        // register part: k in [0, 104) -> 26 LDS.128 broadcasts
        #pragma unroll
        for (int q = 0; q < REGK / 4; q++) {
            ulonglong2 hh = hb2[q];
            fma2(aA0, wA[2 * q],     hh.x); fma2(aB0, wB[2 * q],     hh.x);
            fma2(aA1, wA[2 * q + 1], hh.y); fma2(aB1, wB[2 * q + 1], hh.y);
        }
        // SMEM fp16 part: k in [104, 128), 3 groups of 8 cols
        #pragma unroll
        for (int q = 0; q < NW64; q++) {
            ulonglong2 hh0 = hb2[REGK / 4 + 2 * q];       // h[104+8q..107+8q]
            ulonglong2 hh1 = hb2[REGK / 4 + 2 * q + 1];   // h[108+8q..111+8q]
            u64 waLo = wsh[q * 512 + rA];
            u64 waHi = wsh[(NW64 + q) * 512 + rA];
            u64 wbLo = wsh[q * 512 + rB];
            u64 wbHi = wsh[(NW64 + q) * 512 + rB];
            fma2(aA0, h2f2((unsigned int)waLo),         hh0.x);
            fma2(aA1, h2f2((unsigned int)(waLo >> 32)), hh0.y);
            fma2(aA0, h2f2((unsigned int)waHi),         hh1.x);
            fma2(aA1, h2f2((unsigned int)(waHi >> 32)), hh1.y);
            fma2(aB0, h2f2((unsigned int)wbLo),         hh0.x);
            fma2(aB1, h2f2((unsigned int)(wbLo >> 32)), hh0.y);
            fma2(aB0, h2f2((unsigned int)wbHi),         hh1.x);
            fma2(aB1, h2f2((unsigned int)(wbHi >> 32)), hh1.y);
        }

        float s0, s1, s2, s3;
        upk(aA0, s0, s1); upk(aA1, s2, s3);
        float gA = xa + (s0 + s1) + (s2 + s3);
        upk(aB0, s0, s1); upk(aB1, s2, s3);
        float gB = xb + (s0 + s1) + (s2 + s3);

        // distributed activations (HW tanh), gathered as float4 {i,g,f,o}:
        float act0 = sigmoid_ap(gA);
        float act1 = (tid < 128) ? tanh_ap(gB) : sigmoid_ap(gB);
        {
            float2* dst = (float2*)&gQ[4 * jh + ((tid < 128) ? 0 : 2)];
            *dst = make_float2(act0, act1);
        }
        __syncthreads();

        // phase B (redundant across the partner pair; c stays consistent)
        float4 q4 = *(const float4*)&gQ[4 * jh];   // {i, g, f, o}
        c = q4.z * c + q4.x * q4.y;
        if (tid < 128) {
            float hn = q4.w * tanh_ap(c);
            h_s[(p ^ 1) * HH + jh] = hn;
            enc[(size_t)t * HH + jh] = hn;
        }
        __syncthreads();
        p ^= 1;
    }

    if (tid < HH) out[b * HH + tid] = h_s[p * HH + tid];   // h_last
}

extern "C" void kernel_launch(void* const* d_in, const int* in_sizes, int n_in,
                              void* d_out, int out_size) {
    const float* x    = (const float*)d_in[0];   // [B,T,I]
    const float* h0   = (const float*)d_in[1];   // [B,H]
    const float* c0   = (const float*)d_in[2];   // [B,H]
    const float* Wih  = (const float*)d_in[3];   // [4H,I]
    const float* Whh  = (const float*)d_in[4];   // [4H,H]
    const float* bih  = (const float*)d_in[5];   // [4H]
    const float* bhh  = (const float*)d_in[6];   // [4H]
    float* out = (float*)d_out;                  // [B*H] h_last, then [B,T,H]

    constexpr int SMEM1 = (64 * 512 + 512 + 64 * 68) * 4;             // 150528
    constexpr int SMEM2 = 2 * NW64 * 512 * 8 + 2 * HH * 4 + HH * 16;  // 27648

    cudaFuncSetAttribute(xproj_kernel,
        cudaFuncAttributeMaxDynamicSharedMemorySize, SMEM1);
    cudaFuncSetAttribute(lstm_kernel,
        cudaFuncAttributeMaxDynamicSharedMemorySize, SMEM2);

    xproj_kernel<<<148, 512, SMEM1>>>(x, Wih, bih, bhh);
    lstm_kernel<<<BB, 256, SMEM2>>>(Whh, h0, c0, out);
}